// round 9
// baseline (speedup 1.0000x reference)
#include <cuda_runtime.h>
#include <cuda_bf16.h>
#include <math.h>
#include <stdint.h>

#define Bn 512
#define Cn 1000
#define CP 1024
#define Dn 512
#define Kn 10
#define ZS 4                 // K-split factor
#define KEXT 3072
#define KL (KEXT / ZS)       // 768 per split
#define BKC 64               // K-chunk (bf16 elems)
#define NCH (KL / BKC)       // 12 chunks
#define TM 128
#define TN 128
#define ASTAGE (TM * BKC * 2)   // 16384 B
#define BSTAGE (TN * BKC * 2)   // 16384 B
#define GRID2 128            // fused gemm+topk grid (all co-resident)

// Scratch (device globals — zero-initialized, no allocations allowed)
__device__ __nv_bfloat16 g_Aext[Bn * KEXT];   // [b][3072]
__device__ __nv_bfloat16 g_Bext[CP * KEXT];   // [c][3072] (rows >= Cn stay zero)
__device__ float g_Cc[CP];
__device__ float g_simiP[ZS * Bn * Cn];
__device__ unsigned g_bar;                    // grid barrier (self-resetting)
__device__ unsigned g_rst;

// ---------------------------------------------------------------------------
// helpers
// ---------------------------------------------------------------------------
__device__ __forceinline__ float fsqrt_approx(float v) {
    float r; asm("sqrt.approx.f32 %0, %1;" : "=f"(r) : "f"(v)); return r;
}
// exp(t) for t <= 0, FMA-pipe only (no MUFU/CVT). ~1e-7 rel err.
__device__ __forceinline__ float exp_fma(float t) {
    t = fmaxf(t * 1.4426950408889634f, -80.0f);     // log2(e), clamp
    const float M = 12582912.0f;                     // 2^23 + 2^22
    float m = t + M;
    int nsh = __float_as_int(m) << 23;               // n << 23 (two's compl ok)
    float r = t - (m - M);                           // r in [-0.5, 0.5]
    float p = 0.0013333558f;
    p = fmaf(p, r, 0.0096181291f);
    p = fmaf(p, r, 0.0555041087f);
    p = fmaf(p, r, 0.2402265069f);
    p = fmaf(p, r, 0.6931471806f);
    p = fmaf(p, r, 1.0f);
    return __int_as_float(__float_as_int(p) + nsh);
}
__device__ __forceinline__ void bsplit(float a, __nv_bfloat16& h, __nv_bfloat16& l) {
    h = __float2bfloat16(a);
    l = __float2bfloat16(a - __bfloat162float(h));
}
__device__ __forceinline__ void st4b(__nv_bfloat16* dst,
                                     __nv_bfloat16 a, __nv_bfloat16 b,
                                     __nv_bfloat16 c, __nv_bfloat16 d) {
    __nv_bfloat162 p0 = __halves2bfloat162(a, b);
    __nv_bfloat162 p1 = __halves2bfloat162(c, d);
    uint2 u;
    u.x = *reinterpret_cast<unsigned*>(&p0);
    u.y = *reinterpret_cast<unsigned*>(&p1);
    *reinterpret_cast<uint2*>(dst) = u;
}
__device__ __forceinline__ uint32_t smem_u32(const void* p) {
    uint32_t a;
    asm("{ .reg .u64 t; cvta.to.shared.u64 t, %1; cvt.u32.u64 %0, t; }"
        : "=r"(a) : "l"(p));
    return a;
}

#define LDSM4(r0, r1, r2, r3, addr)                                            \
    asm volatile("ldmatrix.sync.aligned.m8n8.x4.shared.b16 {%0,%1,%2,%3}, [%4];" \
                 : "=r"(r0), "=r"(r1), "=r"(r2), "=r"(r3) : "r"(addr))

#define MMA16816(d, a0, a1, a2, a3, b0, b1)                                    \
    asm volatile("mma.sync.aligned.m16n8k16.row.col.f32.bf16.bf16.f32 "        \
                 "{%0,%1,%2,%3}, {%4,%5,%6,%7}, {%8,%9}, {%0,%1,%2,%3};"       \
                 : "+f"(d[0]), "+f"(d[1]), "+f"(d[2]), "+f"(d[3])              \
                 : "r"(a0), "r"(a1), "r"(a2), "r"(a3), "r"(b0), "r"(b1))

// ---------------------------------------------------------------------------
// Kernel 1: ONE WARP per unit. Units [0,Bn): pack x row -> A_ext.
// Units [Bn, Bn+Cn): per-class softmax prep -> B_ext + Cc.
// Shuffle-only reductions (no __syncthreads), FMA-pipe exp.
// A_ext row layout (3072): [hi(x2)|hi(x)|hi(x2)|hi(x)|lo(x2)|lo(x)]
// B_ext row layout (3072): [hi(w)|hi(wp)|lo(w)|lo(wp)|hi(w)|hi(wp)]
// ---------------------------------------------------------------------------
__global__ void __launch_bounds__(128) prep_kernel(
        const float* __restrict__ x,
        const float* __restrict__ protos,
        const float* __restrict__ ex2,
        const float* __restrict__ ex1,
        const int*   __restrict__ cls_num) {
    const int gw   = blockIdx.x * 4 + (threadIdx.x >> 5);
    const int lane = threadIdx.x & 31;

    if (gw < Bn) {
        // ---- pack x ----
        const int b = gw;
        const float* xr = x + (size_t)b * Dn;
        __nv_bfloat16* arow = g_Aext + (size_t)b * KEXT;
#pragma unroll
        for (int i = 0; i < 4; i++) {
            const int d = i * 128 + lane * 4;
            const float4 xv = *reinterpret_cast<const float4*>(xr + d);
            const float xs[4] = {xv.x, xv.y, xv.z, xv.w};
            __nv_bfloat16 x2h[4], x2l[4], xh[4], xl[4];
#pragma unroll
            for (int j = 0; j < 4; j++) {
                bsplit(xs[j] * xs[j], x2h[j], x2l[j]);
                bsplit(xs[j],         xh[j],  xl[j]);
            }
            st4b(arow + 0    + d, x2h[0], x2h[1], x2h[2], x2h[3]);
            st4b(arow + 512  + d, xh[0],  xh[1],  xh[2],  xh[3]);
            st4b(arow + 1024 + d, x2h[0], x2h[1], x2h[2], x2h[3]);
            st4b(arow + 1536 + d, xh[0],  xh[1],  xh[2],  xh[3]);
            st4b(arow + 2048 + d, x2l[0], x2l[1], x2l[2], x2l[3]);
            st4b(arow + 2560 + d, xl[0],  xl[1],  xl[2],  xl[3]);
        }
        return;
    }

    // ---- per-class softmax prep ----
    const int c = gw - Bn;
    const float N = (float)cls_num[c];
    const float* e2r = ex2 + (size_t)c * Dn;
    const float* e1r = ex1 + (size_t)c * Dn;

    float rd[4][4];
    float mn = INFINITY;
#pragma unroll
    for (int i = 0; i < 4; i++) {
        const int d = i * 128 + lane * 4;
        const float4 e2 = *reinterpret_cast<const float4*>(e2r + d);
        const float4 e1 = *reinterpret_cast<const float4*>(e1r + d);
        rd[i][0] = fsqrt_approx(N * e2.x * e2.x - e1.x * e1.x);
        rd[i][1] = fsqrt_approx(N * e2.y * e2.y - e1.y * e1.y);
        rd[i][2] = fsqrt_approx(N * e2.z * e2.z - e1.z * e1.z);
        rd[i][3] = fsqrt_approx(N * e2.w * e2.w - e1.w * e1.w);
        mn = fminf(mn, fminf(fminf(rd[i][0], rd[i][1]), fminf(rd[i][2], rd[i][3])));
    }
#pragma unroll
    for (int off = 16; off; off >>= 1)
        mn = fminf(mn, __shfl_xor_sync(0xffffffffu, mn, off));

    float e[4][4];
    float lsum = 0.f;
#pragma unroll
    for (int i = 0; i < 4; i++)
#pragma unroll
        for (int j = 0; j < 4; j++) {
            e[i][j] = exp_fma(mn - rd[i][j]);
            lsum += e[i][j];
        }
#pragma unroll
    for (int off = 16; off; off >>= 1)
        lsum += __shfl_xor_sync(0xffffffffu, lsum, off);
    const float inv = 1.0f / lsum;

    __nv_bfloat16* brow = g_Bext + (size_t)c * KEXT;
    float csum = 0.f;
#pragma unroll
    for (int i = 0; i < 4; i++) {
        const int d = i * 128 + lane * 4;
        const float4 p = *reinterpret_cast<const float4*>(protos + (size_t)c * Dn + d);
        const float pv[4] = {p.x, p.y, p.z, p.w};
        __nv_bfloat16 wh[4], wl[4], ph[4], pl[4];
#pragma unroll
        for (int j = 0; j < 4; j++) {
            float w  = e[i][j] * inv;
            float wp = -2.0f * w * pv[j];
            bsplit(w,  wh[j], wl[j]);
            bsplit(wp, ph[j], pl[j]);
            csum += w * pv[j] * pv[j];
        }
        st4b(brow + 0    + d, wh[0], wh[1], wh[2], wh[3]);
        st4b(brow + 512  + d, ph[0], ph[1], ph[2], ph[3]);
        st4b(brow + 1024 + d, wl[0], wl[1], wl[2], wl[3]);
        st4b(brow + 1536 + d, pl[0], pl[1], pl[2], pl[3]);
        st4b(brow + 2048 + d, wh[0], wh[1], wh[2], wh[3]);
        st4b(brow + 2560 + d, ph[0], ph[1], ph[2], ph[3]);
    }
#pragma unroll
    for (int off = 16; off; off >>= 1)
        csum += __shfl_xor_sync(0xffffffffu, csum, off);
    if (lane == 0) g_Cc[c] = csum;
}

// ---------------------------------------------------------------------------
// Kernel 2 (fused): HMMA bf16 GEMM (128x128 tile, K-split x4) -> grid barrier
// -> topk (4 rows per CTA, 8 warps/row, float4 loads).
// Output: out[0..B) = predict (float labels), out[B + b*K + k] = conf.
// ---------------------------------------------------------------------------
__global__ void __launch_bounds__(256, 1) gemm_topk_kernel(
        const int* __restrict__ proto_label, float* __restrict__ out) {
    extern __shared__ char dsm[];
    const uint32_t sbase = smem_u32(dsm);
    const uint32_t aS = (sbase + 1023) & ~1023u;
    const uint32_t bS = aS + 2 * ASTAGE;

    const int tid  = threadIdx.x;
    const int lane = tid & 31;
    const int w    = tid >> 5;                     // 0..7
    const int wrow = w >> 2;                       // 0..1 (M)
    const int wcol = w & 3;                        // 0..3 (N)
    const int bid  = blockIdx.x;                   // 0..127
    const int c0 = (bid & 7) * TN;
    const int b0 = ((bid >> 3) & 3) * TM;
    const int z  = bid >> 5;                       // 0..3
    const int kbase = z * KL;

    // ================= GEMM phase =================
    uint32_t aAddr[4];
    {
        const int sel = (lane >> 4) * 16;
#pragma unroll
        for (int mt = 0; mt < 4; mt++) {
            const int row = wrow * 64 + mt * 16 + (lane & 15);
            aAddr[mt] = row * 128 + (((row & 7) * 16) ^ sel);
        }
    }
    uint32_t bAddr[2];
    {
        const int sel = ((lane >> 3) & 1) * 16;
#pragma unroll
        for (int np = 0; np < 2; np++) {
            const int row = wcol * 32 + np * 16 + (lane & 7) + ((lane >> 4) << 3);
            bAddr[np] = row * 128 + (((row & 7) * 16) ^ sel);
        }
    }

#define LOAD_CHUNK(ci, pp) do {                                                     \
    const int _koff = kbase + (ci) * BKC;                                           \
    _Pragma("unroll")                                                               \
    for (int _t = 0; _t < 4; _t++) {                                                \
        const int _idx = tid + _t * 256;                                            \
        const int _row = _idx >> 3, _seg = _idx & 7;                                \
        const __nv_bfloat16* _srcA =                                                \
            g_Aext + (size_t)(b0 + _row) * KEXT + _koff + _seg * 8;                 \
        const uint32_t _dA = aS + (pp) * ASTAGE + _row * 128 +                      \
                             ((_seg * 16) ^ ((_row & 7) * 16));                     \
        asm volatile("cp.async.cg.shared.global [%0], [%1], 16;"                    \
                     :: "r"(_dA), "l"(_srcA) : "memory");                           \
        const __nv_bfloat16* _srcB =                                                \
            g_Bext + (size_t)(c0 + _row) * KEXT + _koff + _seg * 8;                 \
        const uint32_t _dB = bS + (pp) * BSTAGE + _row * 128 +                      \
                             ((_seg * 16) ^ ((_row & 7) * 16));                     \
        asm volatile("cp.async.cg.shared.global [%0], [%1], 16;"                    \
                     :: "r"(_dB), "l"(_srcB) : "memory");                           \
    }                                                                               \
    asm volatile("cp.async.commit_group;" ::: "memory");                            \
} while (0)

    float acc[4][4][4];
#pragma unroll
    for (int i = 0; i < 4; i++)
#pragma unroll
        for (int j = 0; j < 4; j++)
#pragma unroll
            for (int r = 0; r < 4; r++) acc[i][j][r] = 0.f;

    LOAD_CHUNK(0, 0);

    for (int i = 0; i < NCH; i++) {
        const int p = i & 1;
        if (i + 1 < NCH) {
            LOAD_CHUNK(i + 1, p ^ 1);
            asm volatile("cp.async.wait_group 1;" ::: "memory");
        } else {
            asm volatile("cp.async.wait_group 0;" ::: "memory");
        }
        __syncthreads();

        const uint32_t aB = aS + p * ASTAGE;
        const uint32_t bB = bS + p * BSTAGE;
#pragma unroll
        for (int kk = 0; kk < BKC / 16; kk++) {
            const uint32_t ko = kk * 32;
            uint32_t af[4][4], bf[2][4];
#pragma unroll
            for (int mt = 0; mt < 4; mt++) {
                const uint32_t rowterm = aAddr[mt] & ~0x7Fu;
                const uint32_t mix     = aAddr[mt] & 0x7Fu;
                LDSM4(af[mt][0], af[mt][1], af[mt][2], af[mt][3],
                      aB + rowterm + (mix ^ ko));
            }
#pragma unroll
            for (int np = 0; np < 2; np++) {
                const uint32_t rowterm = bAddr[np] & ~0x7Fu;
                const uint32_t mix     = bAddr[np] & 0x7Fu;
                LDSM4(bf[np][0], bf[np][1], bf[np][2], bf[np][3],
                      bB + rowterm + (mix ^ ko));
            }
#pragma unroll
            for (int mt = 0; mt < 4; mt++) {
#pragma unroll
                for (int np = 0; np < 2; np++) {
                    MMA16816(acc[mt][np * 2 + 0],
                             af[mt][0], af[mt][1], af[mt][2], af[mt][3],
                             bf[np][0], bf[np][1]);
                    MMA16816(acc[mt][np * 2 + 1],
                             af[mt][0], af[mt][1], af[mt][2], af[mt][3],
                             bf[np][2], bf[np][3]);
                }
            }
        }
        __syncthreads();
    }

    float* basez = g_simiP + (size_t)z * (Bn * Cn);
#pragma unroll
    for (int mt = 0; mt < 4; mt++) {
        const int m = b0 + wrow * 64 + mt * 16 + (lane >> 2);
#pragma unroll
        for (int nt = 0; nt < 4; nt++) {
            const int n = c0 + wcol * 32 + nt * 8 + (lane & 3) * 2;
            if (n < Cn) {
                float2 v0 = make_float2(acc[mt][nt][0], acc[mt][nt][1]);
                float2 v1 = make_float2(acc[mt][nt][2], acc[mt][nt][3]);
                *reinterpret_cast<float2*>(basez + (size_t)m * Cn + n) = v0;
                *reinterpret_cast<float2*>(basez + (size_t)(m + 8) * Cn + n) = v1;
            }
        }
    }
#undef LOAD_CHUNK

    // ================= grid barrier =================
    __syncthreads();
    if (tid == 0) {
        __threadfence();
        atomicAdd(&g_bar, 1u);
        while (*(volatile unsigned*)&g_bar < (unsigned)GRID2) {
            __nanosleep(64);
        }
    }
    __syncthreads();
    __threadfence();

    // ================= topk phase =================
    __shared__ float s_v[8][Kn];
    __shared__ int   s_i[8][Kn];

    for (int q = 0; q < 4; q++) {
        const int r = bid * 4 + q;          // row
        const int cbase = w * 128 + lane * 4;

        float v[4] = {INFINITY, INFINITY, INFINITY, INFINITY};
        if (cbase < Cn) {                   // Cn % 4 == 0
            float4 a = *reinterpret_cast<const float4*>(g_Cc + cbase);
#pragma unroll
            for (int zz = 0; zz < ZS; zz++) {
                const float4 p = *reinterpret_cast<const float4*>(
                    g_simiP + (size_t)zz * (Bn * Cn) + (size_t)r * Cn + cbase);
                a.x += p.x; a.y += p.y; a.z += p.z; a.w += p.w;
            }
            v[0] = a.x; v[1] = a.y; v[2] = a.z; v[3] = a.w;
        }

        float tv[4] = {INFINITY, INFINITY, INFINITY, INFINITY};
        int   tix[4] = {0x7fffffff, 0x7fffffff, 0x7fffffff, 0x7fffffff};
#pragma unroll
        for (int e = 0; e < 4; e++) {
            float cv = v[e]; int ci = cbase + e;
#pragma unroll
            for (int i = 0; i < 4; i++) {
                if (cv < tv[i]) {
                    float fv = tv[i]; tv[i] = cv; cv = fv;
                    int   fi = tix[i]; tix[i] = ci; ci = fi;
                }
            }
        }

#pragma unroll
        for (int k = 0; k < Kn; k++) {
            float bv = tv[0]; int bi = tix[0];
#pragma unroll
            for (int off = 16; off; off >>= 1) {
                float ov = __shfl_down_sync(0xffffffffu, bv, off);
                int   oi = __shfl_down_sync(0xffffffffu, bi, off);
                if (ov < bv || (ov == bv && oi < bi)) { bv = ov; bi = oi; }
            }
            bv = __shfl_sync(0xffffffffu, bv, 0);
            bi = __shfl_sync(0xffffffffu, bi, 0);
            if (lane == 0) { s_v[w][k] = bv; s_i[w][k] = bi; }
            if (tix[0] == bi) {
#pragma unroll
                for (int i = 0; i < 3; i++) { tv[i] = tv[i + 1]; tix[i] = tix[i + 1]; }
                tv[3] = INFINITY; tix[3] = 0x7fffffff;
            }
        }
        __syncthreads();

        if (tid == 0) {
            int ptr[8] = {0, 0, 0, 0, 0, 0, 0, 0};
            float sel_v[Kn]; int sel_i[Kn];
#pragma unroll
            for (int k = 0; k < Kn; k++) {
                float bv = INFINITY; int bw = 0;
#pragma unroll
                for (int wq = 0; wq < 8; wq++) {
                    float hv = (ptr[wq] < Kn) ? s_v[wq][ptr[wq]] : INFINITY;
                    if (hv < bv) { bv = hv; bw = wq; }
                }
                sel_v[k] = bv;
                sel_i[k] = s_i[bw][ptr[bw]];
                ptr[bw]++;
            }
            float S = 0.f;
#pragma unroll
            for (int k = 0; k < Kn; k++) S += sel_v[k];
            float bestc = -INFINITY; int bestk = 0;
#pragma unroll
            for (int k = 0; k < Kn; k++) {
                float conf = S / sel_v[k];
                out[Bn + r * Kn + k] = conf;
                if (conf > bestc) { bestc = conf; bestk = k; }
            }
            out[r] = (float)proto_label[sel_i[bestk]];
        }
        __syncthreads();   // protect s_v/s_i reuse next q
    }

    // ---- self-reset barrier counters for next graph replay ----
    if (tid == 0) {
        unsigned vv = atomicAdd(&g_rst, 1u);
        if (vv == (unsigned)(GRID2 - 1)) {
            g_bar = 0u;
            g_rst = 0u;
            __threadfence();
        }
    }
}

// ---------------------------------------------------------------------------
extern "C" void kernel_launch(void* const* d_in, const int* in_sizes, int n_in,
                              void* d_out, int out_size) {
    const float* x           = (const float*)d_in[0];
    const float* protos      = (const float*)d_in[1];
    const float* ex2         = (const float*)d_in[2];
    const float* ex1         = (const float*)d_in[3];
    const int*   cls_num     = (const int*)d_in[4];
    const int*   proto_label = (const int*)d_in[5];
    float* out = (float*)d_out;

    const int smem_sz = 2 * ASTAGE + 2 * BSTAGE + 1024;  // 66560 B
    cudaFuncSetAttribute(gemm_topk_kernel,
                         cudaFuncAttributeMaxDynamicSharedMemorySize, smem_sz);

    prep_kernel<<<(Bn + Cn) / 4, 128>>>(x, protos, ex2, ex1, cls_num);
    gemm_topk_kernel<<<GRID2, 256, smem_sz>>>(proto_label, out);
}

// round 10
// speedup vs baseline: 1.2602x; 1.2602x over previous
#include <cuda_runtime.h>
#include <cuda_bf16.h>
#include <math.h>
#include <stdint.h>

#define Bn 512
#define Cn 1000
#define CP 1024
#define Dn 512
#define Kn 10
#define ZS 4                 // K-split factor
#define KEXT 3072
#define KL (KEXT / ZS)       // 768 per split
#define BKC 64               // K-chunk (bf16 elems)
#define NCH (KL / BKC)       // 12 chunks
#define TM 128
#define TN 64
#define ASTAGE (TM * BKC * 2)   // 16384 B
#define BSTAGE (TN * BKC * 2)   // 8192 B

// Scratch (device globals — zero-initialized, no allocations allowed)
__device__ __nv_bfloat16 g_Aext[Bn * KEXT];   // [b][3072]
__device__ __nv_bfloat16 g_Bext[CP * KEXT];   // [c][3072] (rows >= Cn stay zero)
__device__ float g_Cc[CP];
__device__ float g_simiP[ZS * Bn * Cn];

// ---------------------------------------------------------------------------
// helpers
// ---------------------------------------------------------------------------
__device__ __forceinline__ float fsqrt_approx(float v) {
    float r; asm("sqrt.approx.f32 %0, %1;" : "=f"(r) : "f"(v)); return r;
}
// exp(t) for t <= 0, FMA-pipe only (no MUFU/CVT). ~1e-7 rel err.
__device__ __forceinline__ float exp_fma(float t) {
    t = fmaxf(t * 1.4426950408889634f, -80.0f);
    const float M = 12582912.0f;                     // 2^23 + 2^22
    float m = t + M;
    int nsh = __float_as_int(m) << 23;
    float r = t - (m - M);
    float p = 0.0013333558f;
    p = fmaf(p, r, 0.0096181291f);
    p = fmaf(p, r, 0.0555041087f);
    p = fmaf(p, r, 0.2402265069f);
    p = fmaf(p, r, 0.6931471806f);
    p = fmaf(p, r, 1.0f);
    return __int_as_float(__float_as_int(p) + nsh);
}
__device__ __forceinline__ void bsplit(float a, __nv_bfloat16& h, __nv_bfloat16& l) {
    h = __float2bfloat16(a);
    l = __float2bfloat16(a - __bfloat162float(h));
}
__device__ __forceinline__ void st4b(__nv_bfloat16* dst,
                                     __nv_bfloat16 a, __nv_bfloat16 b,
                                     __nv_bfloat16 c, __nv_bfloat16 d) {
    __nv_bfloat162 p0 = __halves2bfloat162(a, b);
    __nv_bfloat162 p1 = __halves2bfloat162(c, d);
    uint2 u;
    u.x = *reinterpret_cast<unsigned*>(&p0);
    u.y = *reinterpret_cast<unsigned*>(&p1);
    *reinterpret_cast<uint2*>(dst) = u;
}
__device__ __forceinline__ uint32_t smem_u32(const void* p) {
    uint32_t a;
    asm("{ .reg .u64 t; cvta.to.shared.u64 t, %1; cvt.u32.u64 %0, t; }"
        : "=r"(a) : "l"(p));
    return a;
}

#define LDSM4(r0, r1, r2, r3, addr)                                            \
    asm volatile("ldmatrix.sync.aligned.m8n8.x4.shared.b16 {%0,%1,%2,%3}, [%4];" \
                 : "=r"(r0), "=r"(r1), "=r"(r2), "=r"(r3) : "r"(addr))

#define MMA16816(d, a0, a1, a2, a3, b0, b1)                                    \
    asm volatile("mma.sync.aligned.m16n8k16.row.col.f32.bf16.bf16.f32 "        \
                 "{%0,%1,%2,%3}, {%4,%5,%6,%7}, {%8,%9}, {%0,%1,%2,%3};"       \
                 : "+f"(d[0]), "+f"(d[1]), "+f"(d[2]), "+f"(d[3])              \
                 : "r"(a0), "r"(a1), "r"(a2), "r"(a3), "r"(b0), "r"(b1))

// ---------------------------------------------------------------------------
// Kernel 1: ONE WARP per unit. Units [0,Bn): pack x row -> A_ext.
// Units [Bn, Bn+Cn): per-class softmax prep -> B_ext + Cc.
// Shuffle-only reductions, FMA-pipe exp. (~2.3us measured)
// A_ext row layout (3072): [hi(x2)|hi(x)|hi(x2)|hi(x)|lo(x2)|lo(x)]
// B_ext row layout (3072): [hi(w)|hi(wp)|lo(w)|lo(wp)|hi(w)|hi(wp)]
// => dot over 3072 = hi.hi + lo.hi + hi.lo  (lo.lo dropped, ~2^-17 rel)
// ---------------------------------------------------------------------------
__global__ void __launch_bounds__(128) prep_kernel(
        const float* __restrict__ x,
        const float* __restrict__ protos,
        const float* __restrict__ ex2,
        const float* __restrict__ ex1,
        const int*   __restrict__ cls_num) {
    const int gw   = blockIdx.x * 4 + (threadIdx.x >> 5);
    const int lane = threadIdx.x & 31;

    if (gw < Bn) {
        const int b = gw;
        const float* xr = x + (size_t)b * Dn;
        __nv_bfloat16* arow = g_Aext + (size_t)b * KEXT;
#pragma unroll
        for (int i = 0; i < 4; i++) {
            const int d = i * 128 + lane * 4;
            const float4 xv = *reinterpret_cast<const float4*>(xr + d);
            const float xs[4] = {xv.x, xv.y, xv.z, xv.w};
            __nv_bfloat16 x2h[4], x2l[4], xh[4], xl[4];
#pragma unroll
            for (int j = 0; j < 4; j++) {
                bsplit(xs[j] * xs[j], x2h[j], x2l[j]);
                bsplit(xs[j],         xh[j],  xl[j]);
            }
            st4b(arow + 0    + d, x2h[0], x2h[1], x2h[2], x2h[3]);
            st4b(arow + 512  + d, xh[0],  xh[1],  xh[2],  xh[3]);
            st4b(arow + 1024 + d, x2h[0], x2h[1], x2h[2], x2h[3]);
            st4b(arow + 1536 + d, xh[0],  xh[1],  xh[2],  xh[3]);
            st4b(arow + 2048 + d, x2l[0], x2l[1], x2l[2], x2l[3]);
            st4b(arow + 2560 + d, xl[0],  xl[1],  xl[2],  xl[3]);
        }
        return;
    }

    const int c = gw - Bn;
    const float N = (float)cls_num[c];
    const float* e2r = ex2 + (size_t)c * Dn;
    const float* e1r = ex1 + (size_t)c * Dn;

    float rd[4][4];
    float mn = INFINITY;
#pragma unroll
    for (int i = 0; i < 4; i++) {
        const int d = i * 128 + lane * 4;
        const float4 e2 = *reinterpret_cast<const float4*>(e2r + d);
        const float4 e1 = *reinterpret_cast<const float4*>(e1r + d);
        rd[i][0] = fsqrt_approx(N * e2.x * e2.x - e1.x * e1.x);
        rd[i][1] = fsqrt_approx(N * e2.y * e2.y - e1.y * e1.y);
        rd[i][2] = fsqrt_approx(N * e2.z * e2.z - e1.z * e1.z);
        rd[i][3] = fsqrt_approx(N * e2.w * e2.w - e1.w * e1.w);
        mn = fminf(mn, fminf(fminf(rd[i][0], rd[i][1]), fminf(rd[i][2], rd[i][3])));
    }
#pragma unroll
    for (int off = 16; off; off >>= 1)
        mn = fminf(mn, __shfl_xor_sync(0xffffffffu, mn, off));

    float e[4][4];
    float lsum = 0.f;
#pragma unroll
    for (int i = 0; i < 4; i++)
#pragma unroll
        for (int j = 0; j < 4; j++) {
            e[i][j] = exp_fma(mn - rd[i][j]);
            lsum += e[i][j];
        }
#pragma unroll
    for (int off = 16; off; off >>= 1)
        lsum += __shfl_xor_sync(0xffffffffu, lsum, off);
    const float inv = 1.0f / lsum;

    __nv_bfloat16* brow = g_Bext + (size_t)c * KEXT;
    float csum = 0.f;
#pragma unroll
    for (int i = 0; i < 4; i++) {
        const int d = i * 128 + lane * 4;
        const float4 p = *reinterpret_cast<const float4*>(protos + (size_t)c * Dn + d);
        const float pv[4] = {p.x, p.y, p.z, p.w};
        __nv_bfloat16 wh[4], wl[4], ph[4], pl[4];
#pragma unroll
        for (int j = 0; j < 4; j++) {
            float w  = e[i][j] * inv;
            float wp = -2.0f * w * pv[j];
            bsplit(w,  wh[j], wl[j]);
            bsplit(wp, ph[j], pl[j]);
            csum += w * pv[j] * pv[j];
        }
        st4b(brow + 0    + d, wh[0], wh[1], wh[2], wh[3]);
        st4b(brow + 512  + d, ph[0], ph[1], ph[2], ph[3]);
        st4b(brow + 1024 + d, wl[0], wl[1], wl[2], wl[3]);
        st4b(brow + 1536 + d, pl[0], pl[1], pl[2], pl[3]);
        st4b(brow + 2048 + d, wh[0], wh[1], wh[2], wh[3]);
        st4b(brow + 2560 + d, ph[0], ph[1], ph[2], ph[3]);
    }
#pragma unroll
    for (int off = 16; off; off >>= 1)
        csum += __shfl_xor_sync(0xffffffffu, csum, off);
    if (lane == 0) g_Cc[c] = csum;
}

// ---------------------------------------------------------------------------
// Kernel 2: HMMA bf16 GEMM. 128x64 CTA tile, K-split x4 -> 256 CTAs,
// 2 CTAs/SM (regs<=128, smem 48KB). Warp tile 64x16 (4 m16 x 2 n8).
// ---------------------------------------------------------------------------
__global__ void __launch_bounds__(256, 2) gemm_kernel() {
    extern __shared__ char dsm[];
    const uint32_t sbase = smem_u32(dsm);
    const uint32_t aS = (sbase + 1023) & ~1023u;
    const uint32_t bS = aS + 2 * ASTAGE;

    const int tid  = threadIdx.x;
    const int lane = tid & 31;
    const int w    = tid >> 5;                     // 0..7
    const int wrow = w >> 2;                       // 0..1 -> M offset *64
    const int wcol = w & 3;                        // 0..3 -> N offset *16
    const int c0 = blockIdx.x * TN;
    const int b0 = blockIdx.y * TM;
    const int z  = blockIdx.z;
    const int kbase = z * KL;

    // A: 4 m16 tiles, ldmatrix.x4 each
    uint32_t aAddr[4];
    {
        const int sel = (lane >> 4) * 16;
#pragma unroll
        for (int mt = 0; mt < 4; mt++) {
            const int row = wrow * 64 + mt * 16 + (lane & 15);
            aAddr[mt] = row * 128 + (((row & 7) * 16) ^ sel);
        }
    }
    // B: 1 ldmatrix.x4 covering 16 n-rows (2 n8 tiles) x k16
    uint32_t bAddr;
    {
        const int sel = ((lane >> 3) & 1) * 16;
        const int row = wcol * 16 + (lane & 7) + ((lane >> 4) << 3);
        bAddr = row * 128 + (((row & 7) * 16) ^ sel);
    }

#define LOAD_CHUNK(ci, pp) do {                                                     \
    const int _koff = kbase + (ci) * BKC;                                           \
    _Pragma("unroll")                                                               \
    for (int _t = 0; _t < 4; _t++) {   /* A: 1024 xfers */                          \
        const int _idx = tid + _t * 256;                                            \
        const int _row = _idx >> 3, _seg = _idx & 7;                                \
        const __nv_bfloat16* _srcA =                                                \
            g_Aext + (size_t)(b0 + _row) * KEXT + _koff + _seg * 8;                 \
        const uint32_t _dA = aS + (pp) * ASTAGE + _row * 128 +                      \
                             ((_seg * 16) ^ ((_row & 7) * 16));                     \
        asm volatile("cp.async.cg.shared.global [%0], [%1], 16;"                    \
                     :: "r"(_dA), "l"(_srcA) : "memory");                           \
    }                                                                               \
    _Pragma("unroll")                                                               \
    for (int _t = 0; _t < 2; _t++) {   /* B: 512 xfers */                           \
        const int _idx = tid + _t * 256;                                            \
        const int _row = _idx >> 3, _seg = _idx & 7;                                \
        const __nv_bfloat16* _srcB =                                                \
            g_Bext + (size_t)(c0 + _row) * KEXT + _koff + _seg * 8;                 \
        const uint32_t _dB = bS + (pp) * BSTAGE + _row * 128 +                      \
                             ((_seg * 16) ^ ((_row & 7) * 16));                     \
        asm volatile("cp.async.cg.shared.global [%0], [%1], 16;"                    \
                     :: "r"(_dB), "l"(_srcB) : "memory");                           \
    }                                                                               \
    asm volatile("cp.async.commit_group;" ::: "memory");                            \
} while (0)

    float acc[4][2][4];
#pragma unroll
    for (int i = 0; i < 4; i++)
#pragma unroll
        for (int j = 0; j < 2; j++)
#pragma unroll
            for (int r = 0; r < 4; r++) acc[i][j][r] = 0.f;

    LOAD_CHUNK(0, 0);

    for (int i = 0; i < NCH; i++) {
        const int p = i & 1;
        if (i + 1 < NCH) {
            LOAD_CHUNK(i + 1, p ^ 1);
            asm volatile("cp.async.wait_group 1;" ::: "memory");
        } else {
            asm volatile("cp.async.wait_group 0;" ::: "memory");
        }
        __syncthreads();

        const uint32_t aB = aS + p * ASTAGE;
        const uint32_t bB = bS + p * BSTAGE;
#pragma unroll
        for (int kk = 0; kk < BKC / 16; kk++) {
            const uint32_t ko = kk * 32;
            uint32_t af[4][4], bf[4];
#pragma unroll
            for (int mt = 0; mt < 4; mt++) {
                const uint32_t rowterm = aAddr[mt] & ~0x7Fu;
                const uint32_t mix     = aAddr[mt] & 0x7Fu;
                LDSM4(af[mt][0], af[mt][1], af[mt][2], af[mt][3],
                      aB + rowterm + (mix ^ ko));
            }
            {
                const uint32_t rowterm = bAddr & ~0x7Fu;
                const uint32_t mix     = bAddr & 0x7Fu;
                LDSM4(bf[0], bf[1], bf[2], bf[3],
                      bB + rowterm + (mix ^ ko));
            }
#pragma unroll
            for (int mt = 0; mt < 4; mt++) {
                MMA16816(acc[mt][0],
                         af[mt][0], af[mt][1], af[mt][2], af[mt][3],
                         bf[0], bf[1]);
                MMA16816(acc[mt][1],
                         af[mt][0], af[mt][1], af[mt][2], af[mt][3],
                         bf[2], bf[3]);
            }
        }
        __syncthreads();
    }

    float* basez = g_simiP + (size_t)z * (Bn * Cn);
#pragma unroll
    for (int mt = 0; mt < 4; mt++) {
        const int m = b0 + wrow * 64 + mt * 16 + (lane >> 2);
#pragma unroll
        for (int nt = 0; nt < 2; nt++) {
            const int n = c0 + wcol * 16 + nt * 8 + (lane & 3) * 2;
            if (n < Cn) {
                float2 v0 = make_float2(acc[mt][nt][0], acc[mt][nt][1]);
                float2 v1 = make_float2(acc[mt][nt][2], acc[mt][nt][3]);
                *reinterpret_cast<float2*>(basez + (size_t)m * Cn + n) = v0;
                *reinterpret_cast<float2*>(basez + (size_t)(m + 8) * Cn + n) = v1;
            }
        }
    }
#undef LOAD_CHUNK
}

// ---------------------------------------------------------------------------
// Kernel 3: one BLOCK (8 warps, 256 thr) per row. Lane l of warp w owns 4
// contiguous classes [w*128 + 4l, +4). 5 independent float4 loads (4 z-
// partials + Cc). Per-lane sorted-4, 10 shuffle-argmin rounds, thread 0
// stable 8-way merge.
// Output: out[0..B) = predict (float labels), out[B + b*K + k] = conf.
// ---------------------------------------------------------------------------
__global__ void topk_kernel(const int* __restrict__ proto_label,
                            float* __restrict__ out) {
    const int r    = blockIdx.x;
    const int warp = threadIdx.x >> 5;
    const int lane = threadIdx.x & 31;
    const int cbase = warp * 128 + lane * 4;

    __shared__ float s_v[8][Kn];
    __shared__ int   s_i[8][Kn];

    float v[4] = {INFINITY, INFINITY, INFINITY, INFINITY};
    if (cbase < Cn) {                     // Cn % 4 == 0
        float4 a = *reinterpret_cast<const float4*>(g_Cc + cbase);
#pragma unroll
        for (int z = 0; z < ZS; z++) {
            const float4 p = *reinterpret_cast<const float4*>(
                g_simiP + (size_t)z * (Bn * Cn) + (size_t)r * Cn + cbase);
            a.x += p.x; a.y += p.y; a.z += p.z; a.w += p.w;
        }
        v[0] = a.x; v[1] = a.y; v[2] = a.z; v[3] = a.w;
    }

    float tv[4] = {INFINITY, INFINITY, INFINITY, INFINITY};
    int   tix[4] = {0x7fffffff, 0x7fffffff, 0x7fffffff, 0x7fffffff};
#pragma unroll
    for (int q = 0; q < 4; q++) {
        float cv = v[q]; int ci = cbase + q;
#pragma unroll
        for (int i = 0; i < 4; i++) {
            if (cv < tv[i]) {
                float fv = tv[i]; tv[i] = cv; cv = fv;
                int   fi = tix[i]; tix[i] = ci; ci = fi;
            }
        }
    }

#pragma unroll
    for (int k = 0; k < Kn; k++) {
        float bv = tv[0]; int bi = tix[0];
#pragma unroll
        for (int off = 16; off; off >>= 1) {
            float ov = __shfl_down_sync(0xffffffffu, bv, off);
            int   oi = __shfl_down_sync(0xffffffffu, bi, off);
            if (ov < bv || (ov == bv && oi < bi)) { bv = ov; bi = oi; }
        }
        bv = __shfl_sync(0xffffffffu, bv, 0);
        bi = __shfl_sync(0xffffffffu, bi, 0);
        if (lane == 0) { s_v[warp][k] = bv; s_i[warp][k] = bi; }
        if (tix[0] == bi) {
#pragma unroll
            for (int i = 0; i < 3; i++) { tv[i] = tv[i + 1]; tix[i] = tix[i + 1]; }
            tv[3] = INFINITY; tix[3] = 0x7fffffff;
        }
    }
    __syncthreads();

    if (threadIdx.x == 0) {
        int ptr[8] = {0, 0, 0, 0, 0, 0, 0, 0};
        float sel_v[Kn]; int sel_i[Kn];
#pragma unroll
        for (int k = 0; k < Kn; k++) {
            float bv = INFINITY; int bw = 0;
#pragma unroll
            for (int wq = 0; wq < 8; wq++) {
                float hv = (ptr[wq] < Kn) ? s_v[wq][ptr[wq]] : INFINITY;
                if (hv < bv) { bv = hv; bw = wq; }   // tie -> lowest warp = lowest idx
            }
            sel_v[k] = bv;
            sel_i[k] = s_i[bw][ptr[bw]];
            ptr[bw]++;
        }
        float S = 0.f;
#pragma unroll
        for (int k = 0; k < Kn; k++) S += sel_v[k];
        float bestc = -INFINITY; int bestk = 0;
#pragma unroll
        for (int k = 0; k < Kn; k++) {
            float conf = S / sel_v[k];
            out[Bn + r * Kn + k] = conf;
            if (conf > bestc) { bestc = conf; bestk = k; }
        }
        out[r] = (float)proto_label[sel_i[bestk]];
    }
}

// ---------------------------------------------------------------------------
extern "C" void kernel_launch(void* const* d_in, const int* in_sizes, int n_in,
                              void* d_out, int out_size) {
    const float* x           = (const float*)d_in[0];
    const float* protos      = (const float*)d_in[1];
    const float* ex2         = (const float*)d_in[2];
    const float* ex1         = (const float*)d_in[3];
    const int*   cls_num     = (const int*)d_in[4];
    const int*   proto_label = (const int*)d_in[5];
    float* out = (float*)d_out;

    const int smem_sz = 2 * ASTAGE + 2 * BSTAGE + 1024;  // 50176 B
    cudaFuncSetAttribute(gemm_kernel,
                         cudaFuncAttributeMaxDynamicSharedMemorySize, smem_sz);

    prep_kernel<<<(Bn + Cn) / 4, 128>>>(x, protos, ex2, ex1, cls_num);
    dim3 grid(CP / TN, Bn / TM, ZS);   // 16 x 4 x 4 = 256 CTAs
    gemm_kernel<<<grid, 256, smem_sz>>>();
    topk_kernel<<<Bn, 256>>>(proto_label, out);
}

// round 11
// speedup vs baseline: 1.3747x; 1.0909x over previous
#include <cuda_runtime.h>
#include <cuda_bf16.h>
#include <math.h>
#include <stdint.h>

#define Bn 512
#define Cn 1000
#define CP 1024
#define Dn 512
#define Kn 10
#define ZS 4                 // K-split factor
#define KEXT 3072
#define KL (KEXT / ZS)       // 768 per split
#define BKC 64               // K-chunk (bf16 elems)
#define NCH (KL / BKC)       // 12 chunks
#define TM 128
#define TN 128
#define ASTAGE (TM * BKC * 2)   // 16384 B
#define BSTAGE (TN * BKC * 2)   // 16384 B

// Scratch (device globals — zero-initialized, no allocations allowed)
__device__ __nv_bfloat16 g_Aext[Bn * KEXT];   // [b][3072]
__device__ __nv_bfloat16 g_Bext[CP * KEXT];   // [c][3072] (rows >= Cn stay zero)
__device__ float g_Cc[CP];
__device__ float g_simiP[ZS * Bn * Cn];

// ---------------------------------------------------------------------------
// helpers
// ---------------------------------------------------------------------------
__device__ __forceinline__ float fsqrt_approx(float v) {
    float r; asm("sqrt.approx.f32 %0, %1;" : "=f"(r) : "f"(v)); return r;
}
__device__ __forceinline__ void bsplit(float a, __nv_bfloat16& h, __nv_bfloat16& l) {
    h = __float2bfloat16(a);
    l = __float2bfloat16(a - __bfloat162float(h));
}
__device__ __forceinline__ void st4b(__nv_bfloat16* dst,
                                     __nv_bfloat16 a, __nv_bfloat16 b,
                                     __nv_bfloat16 c, __nv_bfloat16 d) {
    __nv_bfloat162 p0 = __halves2bfloat162(a, b);
    __nv_bfloat162 p1 = __halves2bfloat162(c, d);
    uint2 u;
    u.x = *reinterpret_cast<unsigned*>(&p0);
    u.y = *reinterpret_cast<unsigned*>(&p1);
    *reinterpret_cast<uint2*>(dst) = u;
}
__device__ __forceinline__ uint32_t smem_u32(const void* p) {
    uint32_t a;
    asm("{ .reg .u64 t; cvta.to.shared.u64 t, %1; cvt.u32.u64 %0, t; }"
        : "=r"(a) : "l"(p));
    return a;
}

#define LDSM4(r0, r1, r2, r3, addr)                                            \
    asm volatile("ldmatrix.sync.aligned.m8n8.x4.shared.b16 {%0,%1,%2,%3}, [%4];" \
                 : "=r"(r0), "=r"(r1), "=r"(r2), "=r"(r3) : "r"(addr))

#define MMA16816(d, a0, a1, a2, a3, b0, b1)                                    \
    asm volatile("mma.sync.aligned.m16n8k16.row.col.f32.bf16.bf16.f32 "        \
                 "{%0,%1,%2,%3}, {%4,%5,%6,%7}, {%8,%9}, {%0,%1,%2,%3};"       \
                 : "+f"(d[0]), "+f"(d[1]), "+f"(d[2]), "+f"(d[3])              \
                 : "r"(a0), "r"(a1), "r"(a2), "r"(a3), "r"(b0), "r"(b1))

// ---------------------------------------------------------------------------
// Kernel 1 (fused, block-per-unit): blocks [0, Bn) pack x -> A_ext;
// blocks [Bn, Bn+Cn) per-class softmax prep -> B_ext + Cc. 128 threads each.
// (Measured 6.1us at occ 48% in R7 — best known variant.)
// A_ext row layout (3072): [hi(x2)|hi(x)|hi(x2)|hi(x)|lo(x2)|lo(x)]
// B_ext row layout (3072): [hi(w)|hi(wp)|lo(w)|lo(wp)|hi(w)|hi(wp)]
// => dot over 3072 = hi.hi + lo.hi + hi.lo  (lo.lo dropped, ~2^-17 rel)
// ---------------------------------------------------------------------------
__global__ void prep_kernel(const float* __restrict__ x,
                            const float* __restrict__ protos,
                            const float* __restrict__ ex2,
                            const float* __restrict__ ex1,
                            const int*   __restrict__ cls_num) {
    const int t = threadIdx.x;          // 128

    if (blockIdx.x < Bn) {
        const int b = blockIdx.x;
        const float4 xv = *reinterpret_cast<const float4*>(x + b * Dn + t * 4);
        const float xs[4] = {xv.x, xv.y, xv.z, xv.w};
        __nv_bfloat16 x2h[4], x2l[4], xh[4], xl[4];
#pragma unroll
        for (int i = 0; i < 4; i++) {
            bsplit(xs[i] * xs[i], x2h[i], x2l[i]);
            bsplit(xs[i],         xh[i],  xl[i]);
        }
        __nv_bfloat16* arow = g_Aext + (size_t)b * KEXT + t * 4;
        st4b(arow + 0,    x2h[0], x2h[1], x2h[2], x2h[3]);
        st4b(arow + 512,  xh[0],  xh[1],  xh[2],  xh[3]);
        st4b(arow + 1024, x2h[0], x2h[1], x2h[2], x2h[3]);
        st4b(arow + 1536, xh[0],  xh[1],  xh[2],  xh[3]);
        st4b(arow + 2048, x2l[0], x2l[1], x2l[2], x2l[3]);
        st4b(arow + 2560, xl[0],  xl[1],  xl[2],  xl[3]);
        return;
    }

    const int c = blockIdx.x - Bn;
    const int wid = t >> 5, lane = t & 31;
    const float N = (float)cls_num[c];

    const float4 e2 = *reinterpret_cast<const float4*>(ex2 + c * Dn + t * 4);
    const float4 e1 = *reinterpret_cast<const float4*>(ex1 + c * Dn + t * 4);

    float rd[4];
    rd[0] = fsqrt_approx(N * e2.x * e2.x - e1.x * e1.x);
    rd[1] = fsqrt_approx(N * e2.y * e2.y - e1.y * e1.y);
    rd[2] = fsqrt_approx(N * e2.z * e2.z - e1.z * e1.z);
    rd[3] = fsqrt_approx(N * e2.w * e2.w - e1.w * e1.w);

    float mn = fminf(fminf(rd[0], rd[1]), fminf(rd[2], rd[3]));
#pragma unroll
    for (int off = 16; off; off >>= 1)
        mn = fminf(mn, __shfl_xor_sync(0xffffffffu, mn, off));

    __shared__ float sm[4];
    __shared__ float ss[4];
    if (lane == 0) sm[wid] = mn;
    __syncthreads();
    mn = fminf(fminf(sm[0], sm[1]), fminf(sm[2], sm[3]));

    float e[4], lsum = 0.f;
#pragma unroll
    for (int i = 0; i < 4; i++) { e[i] = __expf(mn - rd[i]); lsum += e[i]; }
#pragma unroll
    for (int off = 16; off; off >>= 1)
        lsum += __shfl_xor_sync(0xffffffffu, lsum, off);
    if (lane == 0) ss[wid] = lsum;
    __syncthreads();
    const float inv = 1.0f / (ss[0] + ss[1] + ss[2] + ss[3]);

    const float4 p = *reinterpret_cast<const float4*>(protos + c * Dn + t * 4);
    const float pv[4] = {p.x, p.y, p.z, p.w};
    __nv_bfloat16 wh[4], wl[4], ph[4], pl[4];
    float csum = 0.f;
#pragma unroll
    for (int i = 0; i < 4; i++) {
        float w  = e[i] * inv;
        float wp = -2.0f * w * pv[i];
        bsplit(w,  wh[i], wl[i]);
        bsplit(wp, ph[i], pl[i]);
        csum += w * pv[i] * pv[i];
    }
    __nv_bfloat16* brow = g_Bext + (size_t)c * KEXT + t * 4;
    st4b(brow + 0,    wh[0], wh[1], wh[2], wh[3]);
    st4b(brow + 512,  ph[0], ph[1], ph[2], ph[3]);
    st4b(brow + 1024, wl[0], wl[1], wl[2], wl[3]);
    st4b(brow + 1536, pl[0], pl[1], pl[2], pl[3]);
    st4b(brow + 2048, wh[0], wh[1], wh[2], wh[3]);
    st4b(brow + 2560, ph[0], ph[1], ph[2], ph[3]);

#pragma unroll
    for (int off = 16; off; off >>= 1)
        csum += __shfl_xor_sync(0xffffffffu, csum, off);
    __syncthreads();
    if (lane == 0) ss[wid] = csum;
    __syncthreads();
    if (t == 0) g_Cc[c] = ss[0] + ss[1] + ss[2] + ss[3];
}

// ---------------------------------------------------------------------------
// Kernel 2: HMMA bf16 GEMM — R6 config: 128x128 CTA tile, K-split x4,
// __launch_bounds__(256,1) (no reg cap -> no spills), grid 128 CTAs.
// ---------------------------------------------------------------------------
__global__ void __launch_bounds__(256, 1) gemm_kernel() {
    extern __shared__ char dsm[];
    const uint32_t sbase = smem_u32(dsm);
    const uint32_t aS = (sbase + 1023) & ~1023u;
    const uint32_t bS = aS + 2 * ASTAGE;

    const int tid  = threadIdx.x;
    const int lane = tid & 31;
    const int w    = tid >> 5;                     // 0..7
    const int wrow = w >> 2;                       // 0..1 (M)
    const int wcol = w & 3;                        // 0..3 (N)
    const int c0 = blockIdx.x * TN;
    const int b0 = blockIdx.y * TM;
    const int z  = blockIdx.z;
    const int kbase = z * KL;

    uint32_t aAddr[4];
    {
        const int sel = (lane >> 4) * 16;
#pragma unroll
        for (int mt = 0; mt < 4; mt++) {
            const int row = wrow * 64 + mt * 16 + (lane & 15);
            aAddr[mt] = row * 128 + (((row & 7) * 16) ^ sel);
        }
    }
    uint32_t bAddr[2];
    {
        const int sel = ((lane >> 3) & 1) * 16;
#pragma unroll
        for (int np = 0; np < 2; np++) {
            const int row = wcol * 32 + np * 16 + (lane & 7) + ((lane >> 4) << 3);
            bAddr[np] = row * 128 + (((row & 7) * 16) ^ sel);
        }
    }

#define LOAD_CHUNK(ci, pp) do {                                                     \
    const int _koff = kbase + (ci) * BKC;                                           \
    _Pragma("unroll")                                                               \
    for (int _t = 0; _t < 4; _t++) {                                                \
        const int _idx = tid + _t * 256;                                            \
        const int _row = _idx >> 3, _seg = _idx & 7;                                \
        const __nv_bfloat16* _srcA =                                                \
            g_Aext + (size_t)(b0 + _row) * KEXT + _koff + _seg * 8;                 \
        const uint32_t _dA = aS + (pp) * ASTAGE + _row * 128 +                      \
                             ((_seg * 16) ^ ((_row & 7) * 16));                     \
        asm volatile("cp.async.cg.shared.global [%0], [%1], 16;"                    \
                     :: "r"(_dA), "l"(_srcA) : "memory");                           \
        const __nv_bfloat16* _srcB =                                                \
            g_Bext + (size_t)(c0 + _row) * KEXT + _koff + _seg * 8;                 \
        const uint32_t _dB = bS + (pp) * BSTAGE + _row * 128 +                      \
                             ((_seg * 16) ^ ((_row & 7) * 16));                     \
        asm volatile("cp.async.cg.shared.global [%0], [%1], 16;"                    \
                     :: "r"(_dB), "l"(_srcB) : "memory");                           \
    }                                                                               \
    asm volatile("cp.async.commit_group;" ::: "memory");                            \
} while (0)

    float acc[4][4][4];
#pragma unroll
    for (int i = 0; i < 4; i++)
#pragma unroll
        for (int j = 0; j < 4; j++)
#pragma unroll
            for (int r = 0; r < 4; r++) acc[i][j][r] = 0.f;

    LOAD_CHUNK(0, 0);

    for (int i = 0; i < NCH; i++) {
        const int p = i & 1;
        if (i + 1 < NCH) {
            LOAD_CHUNK(i + 1, p ^ 1);
            asm volatile("cp.async.wait_group 1;" ::: "memory");
        } else {
            asm volatile("cp.async.wait_group 0;" ::: "memory");
        }
        __syncthreads();

        const uint32_t aB = aS + p * ASTAGE;
        const uint32_t bB = bS + p * BSTAGE;
#pragma unroll
        for (int kk = 0; kk < BKC / 16; kk++) {
            const uint32_t ko = kk * 32;
            uint32_t af[4][4], bf[2][4];
#pragma unroll
            for (int mt = 0; mt < 4; mt++) {
                const uint32_t rowterm = aAddr[mt] & ~0x7Fu;
                const uint32_t mix     = aAddr[mt] & 0x7Fu;
                LDSM4(af[mt][0], af[mt][1], af[mt][2], af[mt][3],
                      aB + rowterm + (mix ^ ko));
            }
#pragma unroll
            for (int np = 0; np < 2; np++) {
                const uint32_t rowterm = bAddr[np] & ~0x7Fu;
                const uint32_t mix     = bAddr[np] & 0x7Fu;
                LDSM4(bf[np][0], bf[np][1], bf[np][2], bf[np][3],
                      bB + rowterm + (mix ^ ko));
            }
#pragma unroll
            for (int mt = 0; mt < 4; mt++) {
#pragma unroll
                for (int np = 0; np < 2; np++) {
                    MMA16816(acc[mt][np * 2 + 0],
                             af[mt][0], af[mt][1], af[mt][2], af[mt][3],
                             bf[np][0], bf[np][1]);
                    MMA16816(acc[mt][np * 2 + 1],
                             af[mt][0], af[mt][1], af[mt][2], af[mt][3],
                             bf[np][2], bf[np][3]);
                }
            }
        }
        __syncthreads();
    }

    float* basez = g_simiP + (size_t)z * (Bn * Cn);
#pragma unroll
    for (int mt = 0; mt < 4; mt++) {
        const int m = b0 + wrow * 64 + mt * 16 + (lane >> 2);
#pragma unroll
        for (int nt = 0; nt < 4; nt++) {
            const int n = c0 + wcol * 32 + nt * 8 + (lane & 3) * 2;
            if (n < Cn) {
                float2 v0 = make_float2(acc[mt][nt][0], acc[mt][nt][1]);
                float2 v1 = make_float2(acc[mt][nt][2], acc[mt][nt][3]);
                *reinterpret_cast<float2*>(basez + (size_t)m * Cn + n) = v0;
                *reinterpret_cast<float2*>(basez + (size_t)(m + 8) * Cn + n) = v1;
            }
        }
    }
#undef LOAD_CHUNK
}

// ---------------------------------------------------------------------------
// Kernel 3: one BLOCK (8 warps, 256 thr) per row. Lane l of warp w owns 4
// contiguous classes [w*128 + 4l, +4). 5 independent float4 loads (4 z-
// partials + Cc). Per-lane sorted-4, 10 shuffle-argmin rounds, thread 0
// stable 8-way merge.
// Output: out[0..B) = predict (float labels), out[B + b*K + k] = conf.
// ---------------------------------------------------------------------------
__global__ void topk_kernel(const int* __restrict__ proto_label,
                            float* __restrict__ out) {
    const int r    = blockIdx.x;
    const int warp = threadIdx.x >> 5;
    const int lane = threadIdx.x & 31;
    const int cbase = warp * 128 + lane * 4;

    __shared__ float s_v[8][Kn];
    __shared__ int   s_i[8][Kn];

    float v[4] = {INFINITY, INFINITY, INFINITY, INFINITY};
    if (cbase < Cn) {                     // Cn % 4 == 0
        float4 a = *reinterpret_cast<const float4*>(g_Cc + cbase);
#pragma unroll
        for (int z = 0; z < ZS; z++) {
            const float4 p = *reinterpret_cast<const float4*>(
                g_simiP + (size_t)z * (Bn * Cn) + (size_t)r * Cn + cbase);
            a.x += p.x; a.y += p.y; a.z += p.z; a.w += p.w;
        }
        v[0] = a.x; v[1] = a.y; v[2] = a.z; v[3] = a.w;
    }

    float tv[4] = {INFINITY, INFINITY, INFINITY, INFINITY};
    int   tix[4] = {0x7fffffff, 0x7fffffff, 0x7fffffff, 0x7fffffff};
#pragma unroll
    for (int q = 0; q < 4; q++) {
        float cv = v[q]; int ci = cbase + q;
#pragma unroll
        for (int i = 0; i < 4; i++) {
            if (cv < tv[i]) {
                float fv = tv[i]; tv[i] = cv; cv = fv;
                int   fi = tix[i]; tix[i] = ci; ci = fi;
            }
        }
    }

#pragma unroll
    for (int k = 0; k < Kn; k++) {
        float bv = tv[0]; int bi = tix[0];
#pragma unroll
        for (int off = 16; off; off >>= 1) {
            float ov = __shfl_down_sync(0xffffffffu, bv, off);
            int   oi = __shfl_down_sync(0xffffffffu, bi, off);
            if (ov < bv || (ov == bv && oi < bi)) { bv = ov; bi = oi; }
        }
        bv = __shfl_sync(0xffffffffu, bv, 0);
        bi = __shfl_sync(0xffffffffu, bi, 0);
        if (lane == 0) { s_v[warp][k] = bv; s_i[warp][k] = bi; }
        if (tix[0] == bi) {
#pragma unroll
            for (int i = 0; i < 3; i++) { tv[i] = tv[i + 1]; tix[i] = tix[i + 1]; }
            tv[3] = INFINITY; tix[3] = 0x7fffffff;
        }
    }
    __syncthreads();

    if (threadIdx.x == 0) {
        int ptr[8] = {0, 0, 0, 0, 0, 0, 0, 0};
        float sel_v[Kn]; int sel_i[Kn];
#pragma unroll
        for (int k = 0; k < Kn; k++) {
            float bv = INFINITY; int bw = 0;
#pragma unroll
            for (int wq = 0; wq < 8; wq++) {
                float hv = (ptr[wq] < Kn) ? s_v[wq][ptr[wq]] : INFINITY;
                if (hv < bv) { bv = hv; bw = wq; }
            }
            sel_v[k] = bv;
            sel_i[k] = s_i[bw][ptr[bw]];
            ptr[bw]++;
        }
        float S = 0.f;
#pragma unroll
        for (int k = 0; k < Kn; k++) S += sel_v[k];
        float bestc = -INFINITY; int bestk = 0;
#pragma unroll
        for (int k = 0; k < Kn; k++) {
            float conf = S / sel_v[k];
            out[Bn + r * Kn + k] = conf;
            if (conf > bestc) { bestc = conf; bestk = k; }
        }
        out[r] = (float)proto_label[sel_i[bestk]];
    }
}

// ---------------------------------------------------------------------------
extern "C" void kernel_launch(void* const* d_in, const int* in_sizes, int n_in,
                              void* d_out, int out_size) {
    const float* x           = (const float*)d_in[0];
    const float* protos      = (const float*)d_in[1];
    const float* ex2         = (const float*)d_in[2];
    const float* ex1         = (const float*)d_in[3];
    const int*   cls_num     = (const int*)d_in[4];
    const int*   proto_label = (const int*)d_in[5];
    float* out = (float*)d_out;

    const int smem_sz = 2 * ASTAGE + 2 * BSTAGE + 1024;  // 66560 B
    cudaFuncSetAttribute(gemm_kernel,
                         cudaFuncAttributeMaxDynamicSharedMemorySize, smem_sz);

    prep_kernel<<<Bn + Cn, 128>>>(x, protos, ex2, ex1, cls_num);
    dim3 grid(CP / TN, Bn / TM, ZS);   // 8 x 4 x 4 = 128 CTAs (one wave)
    gemm_kernel<<<grid, 256, smem_sz>>>();
    topk_kernel<<<Bn, 256>>>(proto_label, out);
}

// round 12
// speedup vs baseline: 1.4623x; 1.0637x over previous
#include <cuda_runtime.h>
#include <cuda_bf16.h>
#include <math.h>
#include <stdint.h>

#define Bn 512
#define Cn 1000
#define CP 1024
#define Dn 512
#define Kn 10
#define ZS 4                 // K-split factor
#define KEXT 3072            // logical K (3 segments of 1024)
#define KPHY 2048            // physical K (hi | lo)
#define KL (KEXT / ZS)       // 768 logical per split
#define BKC 64               // K-chunk (bf16 elems)
#define NCH (KL / BKC)       // 12 chunks
#define TM 128
#define TN 128
#define NSTAGE 3
#define ASTAGE (TM * BKC * 2)   // 16384 B
#define BSTAGE (TN * BKC * 2)   // 16384 B

// Scratch (device globals — zero-initialized, no allocations allowed)
__device__ __nv_bfloat16 g_A[Bn * KPHY];   // [b][2048]: [x2h|xh|x2l|xl] (512 each)
__device__ __nv_bfloat16 g_B[CP * KPHY];   // [c][2048]: [wh|wph|wl|wpl] (rows>=Cn zero)
__device__ float g_Cc[CP];
__device__ float g_simiP[ZS * Bn * Cn];

// Logical K-ext (3072) = [S0: Ahi.Bhi | S1: Ahi.Blo | S2: Alo.Bhi]
//   A phys offset = (s==2 ? 1024 : 0) + (k % 1024)
//   B phys offset = (s==1 ? 1024 : 0) + (k % 1024)
// => dot = hi.hi + hi.lo + lo.hi  (lo.lo dropped, ~2^-17 rel)

// ---------------------------------------------------------------------------
// helpers
// ---------------------------------------------------------------------------
__device__ __forceinline__ float fsqrt_approx(float v) {
    float r; asm("sqrt.approx.f32 %0, %1;" : "=f"(r) : "f"(v)); return r;
}
__device__ __forceinline__ void bsplit(float a, __nv_bfloat16& h, __nv_bfloat16& l) {
    h = __float2bfloat16(a);
    l = __float2bfloat16(a - __bfloat162float(h));
}
__device__ __forceinline__ void st4b(__nv_bfloat16* dst,
                                     __nv_bfloat16 a, __nv_bfloat16 b,
                                     __nv_bfloat16 c, __nv_bfloat16 d) {
    __nv_bfloat162 p0 = __halves2bfloat162(a, b);
    __nv_bfloat162 p1 = __halves2bfloat162(c, d);
    uint2 u;
    u.x = *reinterpret_cast<unsigned*>(&p0);
    u.y = *reinterpret_cast<unsigned*>(&p1);
    *reinterpret_cast<uint2*>(dst) = u;
}
__device__ __forceinline__ uint32_t smem_u32(const void* p) {
    uint32_t a;
    asm("{ .reg .u64 t; cvta.to.shared.u64 t, %1; cvt.u32.u64 %0, t; }"
        : "=r"(a) : "l"(p));
    return a;
}

#define LDSM4(r0, r1, r2, r3, addr)                                            \
    asm volatile("ldmatrix.sync.aligned.m8n8.x4.shared.b16 {%0,%1,%2,%3}, [%4];" \
                 : "=r"(r0), "=r"(r1), "=r"(r2), "=r"(r3) : "r"(addr))

#define MMA16816(d, a0, a1, a2, a3, b0, b1)                                    \
    asm volatile("mma.sync.aligned.m16n8k16.row.col.f32.bf16.bf16.f32 "        \
                 "{%0,%1,%2,%3}, {%4,%5,%6,%7}, {%8,%9}, {%0,%1,%2,%3};"       \
                 : "+f"(d[0]), "+f"(d[1]), "+f"(d[2]), "+f"(d[3])              \
                 : "r"(a0), "r"(a1), "r"(a2), "r"(a3), "r"(b0), "r"(b1))

// ---------------------------------------------------------------------------
// Kernel 1 (fused, block-per-unit): blocks [0, Bn) pack x -> g_A;
// blocks [Bn, Bn+Cn) per-class softmax prep -> g_B + Cc. 128 threads each.
// ---------------------------------------------------------------------------
__global__ void prep_kernel(const float* __restrict__ x,
                            const float* __restrict__ protos,
                            const float* __restrict__ ex2,
                            const float* __restrict__ ex1,
                            const int*   __restrict__ cls_num) {
    const int t = threadIdx.x;          // 128

    if (blockIdx.x < Bn) {
        const int b = blockIdx.x;
        const float4 xv = *reinterpret_cast<const float4*>(x + b * Dn + t * 4);
        const float xs[4] = {xv.x, xv.y, xv.z, xv.w};
        __nv_bfloat16 x2h[4], x2l[4], xh[4], xl[4];
#pragma unroll
        for (int i = 0; i < 4; i++) {
            bsplit(xs[i] * xs[i], x2h[i], x2l[i]);
            bsplit(xs[i],         xh[i],  xl[i]);
        }
        __nv_bfloat16* arow = g_A + (size_t)b * KPHY + t * 4;
        st4b(arow + 0,    x2h[0], x2h[1], x2h[2], x2h[3]);
        st4b(arow + 512,  xh[0],  xh[1],  xh[2],  xh[3]);
        st4b(arow + 1024, x2l[0], x2l[1], x2l[2], x2l[3]);
        st4b(arow + 1536, xl[0],  xl[1],  xl[2],  xl[3]);
        return;
    }

    const int c = blockIdx.x - Bn;
    const int wid = t >> 5, lane = t & 31;
    const float N = (float)cls_num[c];

    const float4 e2 = *reinterpret_cast<const float4*>(ex2 + c * Dn + t * 4);
    const float4 e1 = *reinterpret_cast<const float4*>(ex1 + c * Dn + t * 4);

    float rd[4];
    rd[0] = fsqrt_approx(N * e2.x * e2.x - e1.x * e1.x);
    rd[1] = fsqrt_approx(N * e2.y * e2.y - e1.y * e1.y);
    rd[2] = fsqrt_approx(N * e2.z * e2.z - e1.z * e1.z);
    rd[3] = fsqrt_approx(N * e2.w * e2.w - e1.w * e1.w);

    float mn = fminf(fminf(rd[0], rd[1]), fminf(rd[2], rd[3]));
#pragma unroll
    for (int off = 16; off; off >>= 1)
        mn = fminf(mn, __shfl_xor_sync(0xffffffffu, mn, off));

    __shared__ float sm[4];
    __shared__ float ss[4];
    if (lane == 0) sm[wid] = mn;
    __syncthreads();
    mn = fminf(fminf(sm[0], sm[1]), fminf(sm[2], sm[3]));

    float e[4], lsum = 0.f;
#pragma unroll
    for (int i = 0; i < 4; i++) { e[i] = __expf(mn - rd[i]); lsum += e[i]; }
#pragma unroll
    for (int off = 16; off; off >>= 1)
        lsum += __shfl_xor_sync(0xffffffffu, lsum, off);
    if (lane == 0) ss[wid] = lsum;
    __syncthreads();
    const float inv = 1.0f / (ss[0] + ss[1] + ss[2] + ss[3]);

    const float4 p = *reinterpret_cast<const float4*>(protos + c * Dn + t * 4);
    const float pv[4] = {p.x, p.y, p.z, p.w};
    __nv_bfloat16 wh[4], wl[4], ph[4], pl[4];
    float csum = 0.f;
#pragma unroll
    for (int i = 0; i < 4; i++) {
        float w  = e[i] * inv;
        float wp = -2.0f * w * pv[i];
        bsplit(w,  wh[i], wl[i]);
        bsplit(wp, ph[i], pl[i]);
        csum += w * pv[i] * pv[i];
    }
    __nv_bfloat16* brow = g_B + (size_t)c * KPHY + t * 4;
    st4b(brow + 0,    wh[0], wh[1], wh[2], wh[3]);
    st4b(brow + 512,  ph[0], ph[1], ph[2], ph[3]);
    st4b(brow + 1024, wl[0], wl[1], wl[2], wl[3]);
    st4b(brow + 1536, pl[0], pl[1], pl[2], pl[3]);

#pragma unroll
    for (int off = 16; off; off >>= 1)
        csum += __shfl_xor_sync(0xffffffffu, csum, off);
    __syncthreads();
    if (lane == 0) ss[wid] = csum;
    __syncthreads();
    if (t == 0) g_Cc[c] = ss[0] + ss[1] + ss[2] + ss[3];
}

// ---------------------------------------------------------------------------
// Kernel 2: HMMA bf16 GEMM. 128x128 CTA tile, 512 threads (16 warps/SM),
// warp tile 32x32, 3-stage cp.async pipeline, K-split x4 -> 128 CTAs.
// ---------------------------------------------------------------------------
__global__ void __launch_bounds__(512, 1) gemm_kernel() {
    extern __shared__ char dsm[];
    const uint32_t sbase = smem_u32(dsm);
    const uint32_t aS = (sbase + 1023) & ~1023u;
    const uint32_t bS = aS + NSTAGE * ASTAGE;

    const int tid  = threadIdx.x;
    const int lane = tid & 31;
    const int w    = tid >> 5;                     // 0..15
    const int wrow = w >> 2;                       // 0..3 -> M *32
    const int wcol = w & 3;                        // 0..3 -> N *32
    const int c0 = blockIdx.x * TN;
    const int b0 = blockIdx.y * TM;
    const int z  = blockIdx.z;
    const int kbase = z * KL;

    uint32_t aAddr[2];
    {
        const int sel = (lane >> 4) * 16;
#pragma unroll
        for (int mt = 0; mt < 2; mt++) {
            const int row = wrow * 32 + mt * 16 + (lane & 15);
            aAddr[mt] = row * 128 + (((row & 7) * 16) ^ sel);
        }
    }
    uint32_t bAddr[2];
    {
        const int sel = ((lane >> 3) & 1) * 16;
#pragma unroll
        for (int np = 0; np < 2; np++) {
            const int row = wcol * 32 + np * 16 + (lane & 7) + ((lane >> 4) << 3);
            bAddr[np] = row * 128 + (((row & 7) * 16) ^ sel);
        }
    }

#define LOAD_CHUNK(ci, st) do {                                                     \
    const int _k   = kbase + (ci) * BKC;                                            \
    const int _seg = _k >> 10;                                                      \
    const int _rem = _k & 1023;                                                     \
    const int _aoff = ((_seg == 2) ? 1024 : 0) + _rem;                              \
    const int _boff = ((_seg == 1) ? 1024 : 0) + _rem;                              \
    _Pragma("unroll")                                                               \
    for (int _t = 0; _t < 2; _t++) {   /* A: 1024 xfers over 512 thr */             \
        const int _idx = tid + _t * 512;                                            \
        const int _row = _idx >> 3, _s8 = _idx & 7;                                 \
        const __nv_bfloat16* _srcA =                                                \
            g_A + (size_t)(b0 + _row) * KPHY + _aoff + _s8 * 8;                     \
        const uint32_t _dA = aS + (st) * ASTAGE + _row * 128 +                      \
                             ((_s8 * 16) ^ ((_row & 7) * 16));                      \
        asm volatile("cp.async.cg.shared.global [%0], [%1], 16;"                    \
                     :: "r"(_dA), "l"(_srcA) : "memory");                           \
        const __nv_bfloat16* _srcB =                                                \
            g_B + (size_t)(c0 + _row) * KPHY + _boff + _s8 * 8;                     \
        const uint32_t _dB = bS + (st) * BSTAGE + _row * 128 +                      \
                             ((_s8 * 16) ^ ((_row & 7) * 16));                      \
        asm volatile("cp.async.cg.shared.global [%0], [%1], 16;"                    \
                     :: "r"(_dB), "l"(_srcB) : "memory");                           \
    }                                                                               \
    asm volatile("cp.async.commit_group;" ::: "memory");                            \
} while (0)

    float acc[2][4][4];
#pragma unroll
    for (int i = 0; i < 2; i++)
#pragma unroll
        for (int j = 0; j < 4; j++)
#pragma unroll
            for (int r = 0; r < 4; r++) acc[i][j][r] = 0.f;

    LOAD_CHUNK(0, 0);
    LOAD_CHUNK(1, 1);

    for (int i = 0; i < NCH; i++) {
        const int st = i % NSTAGE;
        if (i + 2 < NCH) {
            LOAD_CHUNK(i + 2, (i + 2) % NSTAGE);
            asm volatile("cp.async.wait_group 2;" ::: "memory");
        } else if (i + 1 < NCH) {
            asm volatile("cp.async.wait_group 1;" ::: "memory");
        } else {
            asm volatile("cp.async.wait_group 0;" ::: "memory");
        }
        __syncthreads();

        const uint32_t aB = aS + st * ASTAGE;
        const uint32_t bB = bS + st * BSTAGE;
#pragma unroll
        for (int kk = 0; kk < BKC / 16; kk++) {
            const uint32_t ko = kk * 32;
            uint32_t af[2][4], bf[2][4];
#pragma unroll
            for (int mt = 0; mt < 2; mt++) {
                const uint32_t rowterm = aAddr[mt] & ~0x7Fu;
                const uint32_t mix     = aAddr[mt] & 0x7Fu;
                LDSM4(af[mt][0], af[mt][1], af[mt][2], af[mt][3],
                      aB + rowterm + (mix ^ ko));
            }
#pragma unroll
            for (int np = 0; np < 2; np++) {
                const uint32_t rowterm = bAddr[np] & ~0x7Fu;
                const uint32_t mix     = bAddr[np] & 0x7Fu;
                LDSM4(bf[np][0], bf[np][1], bf[np][2], bf[np][3],
                      bB + rowterm + (mix ^ ko));
            }
#pragma unroll
            for (int mt = 0; mt < 2; mt++) {
#pragma unroll
                for (int np = 0; np < 2; np++) {
                    MMA16816(acc[mt][np * 2 + 0],
                             af[mt][0], af[mt][1], af[mt][2], af[mt][3],
                             bf[np][0], bf[np][1]);
                    MMA16816(acc[mt][np * 2 + 1],
                             af[mt][0], af[mt][1], af[mt][2], af[mt][3],
                             bf[np][2], bf[np][3]);
                }
            }
        }
        __syncthreads();
    }

    float* basez = g_simiP + (size_t)z * (Bn * Cn);
#pragma unroll
    for (int mt = 0; mt < 2; mt++) {
        const int m = b0 + wrow * 32 + mt * 16 + (lane >> 2);
#pragma unroll
        for (int nt = 0; nt < 4; nt++) {
            const int n = c0 + wcol * 32 + nt * 8 + (lane & 3) * 2;
            if (n < Cn) {
                float2 v0 = make_float2(acc[mt][nt][0], acc[mt][nt][1]);
                float2 v1 = make_float2(acc[mt][nt][2], acc[mt][nt][3]);
                *reinterpret_cast<float2*>(basez + (size_t)m * Cn + n) = v0;
                *reinterpret_cast<float2*>(basez + (size_t)(m + 8) * Cn + n) = v1;
            }
        }
    }
#undef LOAD_CHUNK
}

// ---------------------------------------------------------------------------
// Kernel 3: one BLOCK (8 warps, 256 thr) per row. Lane l of warp w owns 4
// contiguous classes [w*128 + 4l, +4). 5 independent float4 loads. Per-lane
// sorted-4, 10 shuffle-argmin rounds, thread 0 stable 8-way merge.
// Output: out[0..B) = predict (float labels), out[B + b*K + k] = conf.
// ---------------------------------------------------------------------------
__global__ void topk_kernel(const int* __restrict__ proto_label,
                            float* __restrict__ out) {
    const int r    = blockIdx.x;
    const int warp = threadIdx.x >> 5;
    const int lane = threadIdx.x & 31;
    const int cbase = warp * 128 + lane * 4;

    __shared__ float s_v[8][Kn];
    __shared__ int   s_i[8][Kn];

    float v[4] = {INFINITY, INFINITY, INFINITY, INFINITY};
    if (cbase < Cn) {                     // Cn % 4 == 0
        float4 a = *reinterpret_cast<const float4*>(g_Cc + cbase);
#pragma unroll
        for (int z = 0; z < ZS; z++) {
            const float4 p = *reinterpret_cast<const float4*>(
                g_simiP + (size_t)z * (Bn * Cn) + (size_t)r * Cn + cbase);
            a.x += p.x; a.y += p.y; a.z += p.z; a.w += p.w;
        }
        v[0] = a.x; v[1] = a.y; v[2] = a.z; v[3] = a.w;
    }

    float tv[4] = {INFINITY, INFINITY, INFINITY, INFINITY};
    int   tix[4] = {0x7fffffff, 0x7fffffff, 0x7fffffff, 0x7fffffff};
#pragma unroll
    for (int q = 0; q < 4; q++) {
        float cv = v[q]; int ci = cbase + q;
#pragma unroll
        for (int i = 0; i < 4; i++) {
            if (cv < tv[i]) {
                float fv = tv[i]; tv[i] = cv; cv = fv;
                int   fi = tix[i]; tix[i] = ci; ci = fi;
            }
        }
    }

#pragma unroll
    for (int k = 0; k < Kn; k++) {
        float bv = tv[0]; int bi = tix[0];
#pragma unroll
        for (int off = 16; off; off >>= 1) {
            float ov = __shfl_down_sync(0xffffffffu, bv, off);
            int   oi = __shfl_down_sync(0xffffffffu, bi, off);
            if (ov < bv || (ov == bv && oi < bi)) { bv = ov; bi = oi; }
        }
        bv = __shfl_sync(0xffffffffu, bv, 0);
        bi = __shfl_sync(0xffffffffu, bi, 0);
        if (lane == 0) { s_v[warp][k] = bv; s_i[warp][k] = bi; }
        if (tix[0] == bi) {
#pragma unroll
            for (int i = 0; i < 3; i++) { tv[i] = tv[i + 1]; tix[i] = tix[i + 1]; }
            tv[3] = INFINITY; tix[3] = 0x7fffffff;
        }
    }
    __syncthreads();

    if (threadIdx.x == 0) {
        int ptr[8] = {0, 0, 0, 0, 0, 0, 0, 0};
        float sel_v[Kn]; int sel_i[Kn];
#pragma unroll
        for (int k = 0; k < Kn; k++) {
            float bv = INFINITY; int bw = 0;
#pragma unroll
            for (int wq = 0; wq < 8; wq++) {
                float hv = (ptr[wq] < Kn) ? s_v[wq][ptr[wq]] : INFINITY;
                if (hv < bv) { bv = hv; bw = wq; }
            }
            sel_v[k] = bv;
            sel_i[k] = s_i[bw][ptr[bw]];
            ptr[bw]++;
        }
        float S = 0.f;
#pragma unroll
        for (int k = 0; k < Kn; k++) S += sel_v[k];
        float bestc = -INFINITY; int bestk = 0;
#pragma unroll
        for (int k = 0; k < Kn; k++) {
            float conf = S / sel_v[k];
            out[Bn + r * Kn + k] = conf;
            if (conf > bestc) { bestc = conf; bestk = k; }
        }
        out[r] = (float)proto_label[sel_i[bestk]];
    }
}

// ---------------------------------------------------------------------------
extern "C" void kernel_launch(void* const* d_in, const int* in_sizes, int n_in,
                              void* d_out, int out_size) {
    const float* x           = (const float*)d_in[0];
    const float* protos      = (const float*)d_in[1];
    const float* ex2         = (const float*)d_in[2];
    const float* ex1         = (const float*)d_in[3];
    const int*   cls_num     = (const int*)d_in[4];
    const int*   proto_label = (const int*)d_in[5];
    float* out = (float*)d_out;

    const int smem_sz = NSTAGE * (ASTAGE + BSTAGE) + 1024;  // 99328 B
    cudaFuncSetAttribute(gemm_kernel,
                         cudaFuncAttributeMaxDynamicSharedMemorySize, smem_sz);

    prep_kernel<<<Bn + Cn, 128>>>(x, protos, ex2, ex1, cls_num);
    dim3 grid(CP / TN, Bn / TM, ZS);   // 8 x 4 x 4 = 128 CTAs (one wave)
    gemm_kernel<<<grid, 512, smem_sz>>>();
    topk_kernel<<<Bn, 256>>>(proto_label, out);
}